// round 6
// baseline (speedup 1.0000x reference)
#include <cuda_runtime.h>
#include <cuda_bf16.h>
#include <cstdint>
#include <math.h>

#define BB   2
#define SS   4096
#define DIM  1024
#define AD   1024
#define QKV3 (3*AD)

// ---------------------------------------------------------------------------
// Device scratch (no dynamic allocation allowed)
// ---------------------------------------------------------------------------
__device__ __nv_bfloat16 g_xh[(size_t)BB*SS*DIM];    // x hi
__device__ __nv_bfloat16 g_xl[(size_t)BB*SS*DIM];    // x lo
__device__ __nv_bfloat16 g_wh[(size_t)QKV3*DIM];     // W hi
__device__ __nv_bfloat16 g_wl[(size_t)QKV3*DIM];     // W lo
__device__ __nv_bfloat16 g_qh[(size_t)BB*SS*AD];     // Q hi
__device__ __nv_bfloat16 g_ql[(size_t)BB*SS*AD];
__device__ __nv_bfloat16 g_kh[(size_t)BB*SS*AD];     // K hi
__device__ __nv_bfloat16 g_kl[(size_t)BB*SS*AD];
__device__ float         g_v [(size_t)BB*SS*AD];     // V fp32
__device__ __nv_bfloat16 g_vth[(size_t)BB*AD*SS];    // V^T hi  [B,AD,S]
__device__ __nv_bfloat16 g_vtl[(size_t)BB*AD*SS];
__device__ __nv_bfloat16 g_ph[(size_t)BB*SS*SS];     // unnormalized exp hi
__device__ __nv_bfloat16 g_pl[(size_t)BB*SS*SS];     // unnormalized exp lo

// ---------------------------------------------------------------------------
// PTX helpers (compute_103-safe: cp.async + ldmatrix + mma.sync only)
// ---------------------------------------------------------------------------
static __device__ __forceinline__ uint32_t smem_u32(const void* p) {
    uint32_t a;
    asm("{ .reg .u64 t; cvta.to.shared.u64 t, %1; cvt.u32.u64 %0, t; }" : "=r"(a) : "l"(p));
    return a;
}
#define CP_ASYNC16(dst, src) \
    asm volatile("cp.async.cg.shared.global [%0], [%1], 16;" :: "r"(dst), "l"(src))
#define CP_COMMIT() asm volatile("cp.async.commit_group;" ::: "memory")
#define CP_WAIT(n)  asm volatile("cp.async.wait_group %0;" :: "n"(n) : "memory")

static __device__ __forceinline__ void ldsm4(uint32_t& r0, uint32_t& r1, uint32_t& r2, uint32_t& r3, uint32_t addr) {
    asm volatile("ldmatrix.sync.aligned.m8n8.x4.shared.b16 {%0,%1,%2,%3}, [%4];"
                 : "=r"(r0), "=r"(r1), "=r"(r2), "=r"(r3) : "r"(addr));
}
static __device__ __forceinline__ void mma16816(float* c,
                                                uint32_t a0, uint32_t a1, uint32_t a2, uint32_t a3,
                                                uint32_t b0, uint32_t b1) {
    asm volatile("mma.sync.aligned.m16n8k16.row.col.f32.bf16.bf16.f32 "
                 "{%0,%1,%2,%3}, {%4,%5,%6,%7}, {%8,%9}, {%0,%1,%2,%3};"
                 : "+f"(c[0]), "+f"(c[1]), "+f"(c[2]), "+f"(c[3])
                 : "r"(a0), "r"(a1), "r"(a2), "r"(a3), "r"(b0), "r"(b1));
}

static __device__ __forceinline__ void store_split2(__nv_bfloat16* H, __nv_bfloat16* L,
                                                    size_t idx, float v0, float v1) {
    __nv_bfloat162 h = __floats2bfloat162_rn(v0, v1);
    __nv_bfloat162 l = __floats2bfloat162_rn(v0 - __bfloat162float(h.x),
                                             v1 - __bfloat162float(h.y));
    *(__nv_bfloat162*)(H + idx) = h;
    *(__nv_bfloat162*)(L + idx) = l;
}

// ---------------------------------------------------------------------------
// Shared HMMA core: C[128x128] += A[128xK] * B[128xK]^T, bf16x3 emulation.
// 3-stage cp.async pipeline (2 loads in flight during compute).
// smem stage: Ah Al Bh Bl, 128 rows x 80B each (64B data + 16B pad).
// Optional RS: row sums of (Ah+Al) via ones-vector MMA (for PV normalization).
// ---------------------------------------------------------------------------
#define T_BYTES    10240           // 128 rows * 80B
#define STAGE_B    (4*T_BYTES)     // 40960
#define SMEM_TOTAL (3*STAGE_B)     // 122880

static __device__ __forceinline__ void stage_tile(uint32_t sdst, const __nv_bfloat16* src,
                                                  int ld, int tid) {
    #pragma unroll
    for (int i = 0; i < 2; ++i) {
        int ci = tid * 2 + i;              // 0..511
        int r = ci >> 2, c = ci & 3;
        CP_ASYNC16(sdst + r * 80 + c * 16, (const char*)(src + (size_t)r * ld) + c * 16);
    }
}

template<bool RS>
static __device__ __forceinline__ void gemm128(
    const __nv_bfloat16* __restrict__ Ah, const __nv_bfloat16* __restrict__ Al, int lda,
    const __nv_bfloat16* __restrict__ Bh, const __nv_bfloat16* __restrict__ Bl, int ldb,
    int nChunks, char* smem, float acc[16][4], float rsacc[4][4])
{
    const int tid  = threadIdx.x;
    const int lane = tid & 31;
    const int w    = tid >> 5;
    const int m_off = (w >> 2) * 64;
    const int n_off = (w & 3) * 32;
    uint32_t sb = smem_u32(smem);
    const uint32_t ONE2 = 0x3F803F80u;     // packed bf16 {1.0, 1.0}

    // ldmatrix lane-address components
    const uint32_t a_row  = (uint32_t)(lane & 15);
    const uint32_t a_koff = (uint32_t)((lane >> 4) & 1) * 16;
    const uint32_t b_row  = (uint32_t)(((lane >> 4) << 3) + (lane & 7));
    const uint32_t b_koff = (uint32_t)((lane >> 3) & 1) * 16;

    // prefetch stages 0 and 1
    #pragma unroll
    for (int s = 0; s < 2; ++s) {
        uint32_t st = sb + s * STAGE_B;
        stage_tile(st,             Ah + (size_t)s * 32, lda, tid);
        stage_tile(st + T_BYTES,   Al + (size_t)s * 32, lda, tid);
        stage_tile(st + 2*T_BYTES, Bh + (size_t)s * 32, ldb, tid);
        stage_tile(st + 3*T_BYTES, Bl + (size_t)s * 32, ldb, tid);
        CP_COMMIT();
    }

    for (int i = 0; i < nChunks; ++i) {
        CP_WAIT(1);                // stage i complete (stage i+1 may be in flight)
        __syncthreads();           // data visible to all; compute(i-1) fully done
        if (i + 2 < nChunks) {     // overwrite stage (i+2)%3 == (i-1)%3 : safe after sync
            uint32_t st = sb + ((i + 2) % 3) * STAGE_B;
            stage_tile(st,             Ah + (size_t)(i + 2) * 32, lda, tid);
            stage_tile(st + T_BYTES,   Al + (size_t)(i + 2) * 32, lda, tid);
            stage_tile(st + 2*T_BYTES, Bh + (size_t)(i + 2) * 32, ldb, tid);
            stage_tile(st + 3*T_BYTES, Bl + (size_t)(i + 2) * 32, ldb, tid);
            CP_COMMIT();
        }

        uint32_t st = sb + (i % 3) * STAGE_B;
        #pragma unroll
        for (int k16 = 0; k16 < 2; ++k16) {
            uint32_t kb = k16 * 32;       // 16 bf16 = 32 bytes
            uint32_t bh[8], bl[8];
            #pragma unroll
            for (int h = 0; h < 2; ++h) {
                uint32_t addr = st + 2*T_BYTES + (uint32_t)(n_off + h*16 + b_row) * 80 + kb + b_koff;
                ldsm4(bh[h*4], bh[h*4+1], bh[h*4+2], bh[h*4+3], addr);
                ldsm4(bl[h*4], bl[h*4+1], bl[h*4+2], bl[h*4+3], addr + T_BYTES);
            }
            #pragma unroll
            for (int mf = 0; mf < 4; ++mf) {
                uint32_t addr = st + (uint32_t)(m_off + mf*16 + a_row) * 80 + kb + a_koff;
                uint32_t h0, h1, h2, h3, l0, l1, l2, l3;
                ldsm4(h0, h1, h2, h3, addr);
                ldsm4(l0, l1, l2, l3, addr + T_BYTES);
                if (RS) {
                    mma16816(rsacc[mf], h0, h1, h2, h3, ONE2, ONE2);   // Σ Ah
                    mma16816(rsacc[mf], l0, l1, l2, l3, ONE2, ONE2);   // Σ Al
                }
                #pragma unroll
                for (int nf = 0; nf < 4; ++nf) {
                    float* c = acc[mf*4 + nf];
                    uint32_t B0 = bh[nf*2], B1 = bh[nf*2+1];
                    mma16816(c, h0, h1, h2, h3, B0, B1);               // Ah*Bh
                    mma16816(c, h0, h1, h2, h3, bl[nf*2], bl[nf*2+1]); // Ah*Bl
                    mma16816(c, l0, l1, l2, l3, B0, B1);               // Al*Bh
                }
            }
        }
    }
    __syncthreads();
}

// ---------------------------------------------------------------------------
// Split kernels: fp32 -> bf16 hi/lo (device globals referenced in device code)
// ---------------------------------------------------------------------------
__global__ void __launch_bounds__(256) split_x_kernel(const float* __restrict__ s) {
    int i = (blockIdx.x * 256 + threadIdx.x) * 4;
    float4 v = *(const float4*)(s + i);
    store_split2(g_xh, g_xl, i,     v.x, v.y);
    store_split2(g_xh, g_xl, i + 2, v.z, v.w);
}
__global__ void __launch_bounds__(256) split_w_kernel(const float* __restrict__ s) {
    int i = (blockIdx.x * 256 + threadIdx.x) * 4;
    float4 v = *(const float4*)(s + i);
    store_split2(g_wh, g_wl, i,     v.x, v.y);
    store_split2(g_wh, g_wl, i + 2, v.z, v.w);
}

// ---------------------------------------------------------------------------
// QKV GEMM: [8192,3072] = x @ W^T + bias; route N-segments to Q/K split, V fp32
// ---------------------------------------------------------------------------
__global__ void __launch_bounds__(256, 1) qkv_mma(const float* __restrict__ bias) {
    extern __shared__ __align__(128) char sm[];
    const int m0 = blockIdx.y * 128, n0 = blockIdx.x * 128;
    const int lane = threadIdx.x & 31, w = threadIdx.x >> 5;
    const int m_off = (w >> 2) * 64, n_off = (w & 3) * 32;

    float acc[16][4];
    #pragma unroll
    for (int i = 0; i < 16; ++i)
        #pragma unroll
        for (int j = 0; j < 4; ++j) acc[i][j] = 0.0f;
    float rs_dummy[4][4];

    gemm128<false>(g_xh + (size_t)m0 * DIM, g_xl + (size_t)m0 * DIM, DIM,
                   g_wh + (size_t)n0 * DIM, g_wl + (size_t)n0 * DIM, DIM,
                   DIM / 32, sm, acc, rs_dummy);

    #pragma unroll
    for (int mf = 0; mf < 4; ++mf) {
        #pragma unroll
        for (int nf = 0; nf < 4; ++nf) {
            float* c = acc[mf*4 + nf];
            int r  = m0 + m_off + mf*16 + (lane >> 2);
            int cg = n0 + n_off + nf*8 + ((lane & 3) << 1);
            float b0 = bias[cg], b1 = bias[cg + 1];
            float v0 = c[0] + b0, v1 = c[1] + b1;     // row r
            float v2 = c[2] + b0, v3 = c[3] + b1;     // row r+8
            if (cg < AD) {
                store_split2(g_qh, g_ql, (size_t)r * AD + cg,       v0, v1);
                store_split2(g_qh, g_ql, (size_t)(r + 8) * AD + cg, v2, v3);
            } else if (cg < 2*AD) {
                int ck = cg - AD;
                store_split2(g_kh, g_kl, (size_t)r * AD + ck,       v0, v1);
                store_split2(g_kh, g_kl, (size_t)(r + 8) * AD + ck, v2, v3);
            } else {
                int cv = cg - 2*AD;
                *(float2*)(g_v + (size_t)r * AD + cv)       = make_float2(v0, v1);
                *(float2*)(g_v + (size_t)(r + 8) * AD + cv) = make_float2(v2, v3);
            }
        }
    }
}

// ---------------------------------------------------------------------------
// V transpose + split: g_v [B,S,AD] -> g_vth/g_vtl [B,AD,S]
// ---------------------------------------------------------------------------
__global__ void __launch_bounds__(256) vt_split_kernel() {
    __shared__ float t[32][33];
    const int b = blockIdx.z;
    const int k0 = blockIdx.x * 32, n0 = blockIdx.y * 32;
    const int tx = threadIdx.x, ty = threadIdx.y;     // 32 x 8
    const float* V = g_v + (size_t)b * SS * AD;
    #pragma unroll
    for (int j = 0; j < 4; ++j)
        t[ty + j * 8][tx] = V[(size_t)(k0 + ty + j * 8) * AD + n0 + tx];
    __syncthreads();
    #pragma unroll
    for (int j = 0; j < 4; ++j) {
        int n = n0 + ty + j * 8;
        int k = k0 + tx;
        float v = t[tx][ty + j * 8];
        __nv_bfloat16 h = __float2bfloat16(v);
        __nv_bfloat16 l = __float2bfloat16(v - __bfloat162float(h));
        size_t idx = ((size_t)b * AD + n) * SS + k;
        g_vth[idx] = h;
        g_vtl[idx] = l;
    }
}

// ---------------------------------------------------------------------------
// Scores GEMM + fused exp: writes UNNORMALIZED e = exp(s/32) as bf16 hi/lo.
// No max subtraction needed: s/32 ~ N(0,1), overflow bound (s<2816) is far away.
// Diagonal blocks mask j>i to exactly 0 (matches -inf-before-scale reference).
// ---------------------------------------------------------------------------
__global__ void __launch_bounds__(256, 1) scores_mma() {
    const int bx = blockIdx.x, by = blockIdx.y, b = blockIdx.z;
    if (bx > by) return;
    extern __shared__ __align__(128) char sm[];
    const int m0 = by * 128, n0 = bx * 128;
    const int lane = threadIdx.x & 31, w = threadIdx.x >> 5;
    const int m_off = (w >> 2) * 64, n_off = (w & 3) * 32;

    float acc[16][4];
    #pragma unroll
    for (int i = 0; i < 16; ++i)
        #pragma unroll
        for (int j = 0; j < 4; ++j) acc[i][j] = 0.0f;
    float rs_dummy[4][4];

    const size_t qo = ((size_t)b * SS + m0) * AD;
    const size_t ko = ((size_t)b * SS + n0) * AD;
    gemm128<false>(g_qh + qo, g_ql + qo, AD, g_kh + ko, g_kl + ko, AD,
                   AD / 32, sm, acc, rs_dummy);

    __nv_bfloat16* ph = g_ph + (size_t)b * SS * SS;
    __nv_bfloat16* pl = g_pl + (size_t)b * SS * SS;
    const float inv = 1.0f / 32.0f;
    const bool diag = (bx == by);
    #pragma unroll
    for (int mf = 0; mf < 4; ++mf) {
        #pragma unroll
        for (int nf = 0; nf < 4; ++nf) {
            float* c = acc[mf*4 + nf];
            int r  = m0 + m_off + mf*16 + (lane >> 2);
            int cg = n0 + n_off + nf*8 + ((lane & 3) << 1);
            float e0 = expf(c[0] * inv), e1 = expf(c[1] * inv);
            float e2 = expf(c[2] * inv), e3 = expf(c[3] * inv);
            if (diag) {
                if (cg     > r)     e0 = 0.0f;
                if (cg + 1 > r)     e1 = 0.0f;
                if (cg     > r + 8) e2 = 0.0f;
                if (cg + 1 > r + 8) e3 = 0.0f;
            }
            store_split2(ph, pl, (size_t)r * SS + cg,       e0, e1);
            store_split2(ph, pl, (size_t)(r + 8) * SS + cg, e2, e3);
        }
    }
}

// ---------------------------------------------------------------------------
// PV GEMM: y = (E @ V) / rowsum(E), K truncated at causal boundary.
// Row sums computed in-loop via ones-vector MMA (deterministic, no extra pass).
// ---------------------------------------------------------------------------
__global__ void __launch_bounds__(256, 1) pv_mma(float* __restrict__ y) {
    extern __shared__ __align__(128) char sm[];
    const int b = blockIdx.z;
    const int m0 = blockIdx.y * 128, n0 = blockIdx.x * 128;
    const int lane = threadIdx.x & 31, w = threadIdx.x >> 5;
    const int m_off = (w >> 2) * 64, n_off = (w & 3) * 32;

    float acc[16][4];
    #pragma unroll
    for (int i = 0; i < 16; ++i)
        #pragma unroll
        for (int j = 0; j < 4; ++j) acc[i][j] = 0.0f;
    float rs[4][4];
    #pragma unroll
    for (int i = 0; i < 4; ++i)
        #pragma unroll
        for (int j = 0; j < 4; ++j) rs[i][j] = 0.0f;

    const size_t po = ((size_t)b * SS + m0) * SS;
    const size_t vo = ((size_t)b * AD + n0) * SS;
    gemm128<true>(g_ph + po, g_pl + po, SS, g_vth + vo, g_vtl + vo, SS,
                  (blockIdx.y + 1) * 4, sm, acc, rs);

    #pragma unroll
    for (int mf = 0; mf < 4; ++mf) {
        const float i0 = 1.0f / rs[mf][0];     // row r   sum
        const float i1 = 1.0f / rs[mf][2];     // row r+8 sum
        #pragma unroll
        for (int nf = 0; nf < 4; ++nf) {
            float* c = acc[mf*4 + nf];
            int r  = m0 + m_off + mf*16 + (lane >> 2);
            int cg = n0 + n_off + nf*8 + ((lane & 3) << 1);
            *(float2*)(y + ((size_t)b * SS + r) * AD + cg)     = make_float2(c[0] * i0, c[1] * i0);
            *(float2*)(y + ((size_t)b * SS + r + 8) * AD + cg) = make_float2(c[2] * i1, c[3] * i1);
        }
    }
}

// ---------------------------------------------------------------------------
extern "C" void kernel_launch(void* const* d_in, const int* in_sizes, int n_in,
                              void* d_out, int out_size)
{
    const float* x    = (const float*)d_in[0];   // [B,S,DIM]
    const float* W    = (const float*)d_in[1];   // [3*AD, DIM]
    const float* bias = (const float*)d_in[2];   // [3*AD]
    float* y = (float*)d_out;                    // [B,S,AD]

    cudaFuncSetAttribute(qkv_mma,    cudaFuncAttributeMaxDynamicSharedMemorySize, SMEM_TOTAL);
    cudaFuncSetAttribute(scores_mma, cudaFuncAttributeMaxDynamicSharedMemorySize, SMEM_TOTAL);
    cudaFuncSetAttribute(pv_mma,     cudaFuncAttributeMaxDynamicSharedMemorySize, SMEM_TOTAL);

    split_x_kernel<<<(BB*SS*DIM) / 1024, 256>>>(x);
    split_w_kernel<<<(QKV3*DIM) / 1024, 256>>>(W);
    qkv_mma   <<<dim3(QKV3/128, (BB*SS)/128), 256, SMEM_TOTAL>>>(bias);
    vt_split_kernel<<<dim3(SS/32, AD/32, BB), dim3(32, 8)>>>();
    scores_mma<<<dim3(SS/128, SS/128, BB), 256, SMEM_TOTAL>>>();
    pv_mma    <<<dim3(AD/128, SS/128, BB), 256, SMEM_TOTAL>>>(y);
}